// round 8
// baseline (speedup 1.0000x reference)
#include <cuda_runtime.h>
#include <cstddef>
#include <cstdint>

// ---------------- problem constants ----------------
constexpr int B      = 2;
constexpr int C      = 256;
constexpr int H      = 256;
constexpr int W      = 256;
constexpr int NROI   = 1000;
constexpr int PH     = 7;
constexpr int PW     = 7;
constexpr int OUT    = 1024;
constexpr int NCLS   = 11;    // NUM_CLASSES + 1
constexpr int NREG   = 5;
constexpr int D      = C * PH * PW;   // 12544
constexpr int M      = B * NROI;      // 2000
constexpr int HW     = H * W;
constexpr int NSAMP  = PH * PW * 4;   // 196

// ---------------- scratch (static device globals; no allocation) ----------------
__device__ float g_feat_t[(size_t)B * HW * C];   // [B, H, W, C]
__device__ float g_x[(size_t)M * D];             // aligned features (tf32-rounded)
__device__ float g_w1t[(size_t)OUT * D];         // w1 transposed [N,K] (tf32-rounded)
__device__ float g_w2t[(size_t)OUT * OUT];       // w2 transposed
__device__ float g_h1[(size_t)M * OUT];
__device__ float g_h2[(size_t)M * OUT];

// ---------------- helpers ----------------
__device__ __forceinline__ uint32_t smem_u32(const void* p) {
    uint32_t a;
    asm("{ .reg .u64 t; cvta.to.shared.u64 t, %1; cvt.u32.u64 %0, t; }" : "=r"(a) : "l"(p));
    return a;
}
__device__ __forceinline__ float tf32_round(float x) {
    uint32_t u;
    asm("cvt.rna.tf32.f32 %0, %1;" : "=r"(u) : "f"(x));
    return __uint_as_float(u);
}
__device__ __forceinline__ void cpasync16(uint32_t s, const void* g, bool pred) {
    int sz = pred ? 16 : 0;
    asm volatile("cp.async.cg.shared.global [%0], [%1], 16, %2;"
                 :: "r"(s), "l"(g), "r"(sz) : "memory");
}
__device__ __forceinline__ void cp_commit() {
    asm volatile("cp.async.commit_group;" ::: "memory");
}
__device__ __forceinline__ void cp_wait2() {
    asm volatile("cp.async.wait_group 2;" ::: "memory");
}
__device__ __forceinline__ void mma_tf32(float* d, const uint32_t* a, const uint32_t* b) {
    asm volatile(
        "mma.sync.aligned.m16n8k8.row.col.f32.tf32.tf32.f32 "
        "{%0,%1,%2,%3}, {%4,%5,%6,%7}, {%8,%9}, {%0,%1,%2,%3};"
        : "+f"(d[0]), "+f"(d[1]), "+f"(d[2]), "+f"(d[3])
        : "r"(a[0]), "r"(a[1]), "r"(a[2]), "r"(a[3]), "r"(b[0]), "r"(b[1]));
}

// ---------------- 1. generic 32x32 transpose: in[z][R][Cc] -> out[z][Cc][R] ----------------
__global__ void transpose_kernel(const float* __restrict__ in, float* __restrict__ out,
                                 int R, int Cc, int doRound) {
    __shared__ float tile[32][33];
    size_t zo = (size_t)blockIdx.z * R * Cc;
    int c0 = blockIdx.x * 32;
    int r0 = blockIdx.y * 32;
    int tx = threadIdx.x, ty = threadIdx.y;
    #pragma unroll
    for (int i = 0; i < 32; i += 8)
        tile[ty + i][tx] = in[zo + (size_t)(r0 + ty + i) * Cc + c0 + tx];
    __syncthreads();
    #pragma unroll
    for (int i = 0; i < 32; i += 8) {
        float v = tile[tx][ty + i];
        if (doRound) v = tf32_round(v);
        out[zo + (size_t)(c0 + ty + i) * R + r0 + tx] = v;
    }
}

// ---------------- 2. rotated RoI align: geometry + float2 gather ----------------
// one roi per 128-thread block; each thread owns 2 adjacent channels (LDG.64 gathers)
constexpr int ROI_SMEM = D * 4 + NSAMP * 32;   // 56448 B

__global__ void __launch_bounds__(128) roi_align_kernel(const float* __restrict__ rois) {
    extern __shared__ float sacc[];                       // [D]
    uint4*  soff = (uint4*)(sacc + D);                    // [NSAMP]
    float4* swt  = (float4*)(soff + NSAMP);               // [NSAMP]

    int m = blockIdx.x;
    int b = m / NROI;
    int tid = threadIdx.x;

    // ---- Phase A: geometry, 196 samples on 128 threads ----
    for (int s = tid; s < NSAMP; s += 128) {
        const float* rp = rois + (size_t)m * 5;
        float cx = rp[0], cy = rp[1], w = rp[2], h = rp[3], th = rp[4];
        float cosT = cosf(th), sinT = sinf(th);
        float bin_h = h * (1.0f / PH);
        float bin_w = w * (1.0f / PW);

        int bin = s >> 2;            // 0..48
        int sub = s & 3;             // 0..3
        int ph  = bin / PW;
        int pw  = bin % PW;
        int sy  = sub >> 1;
        int sx  = sub & 1;

        float yy = -h * 0.5f + ((float)ph + (sy + 0.5f) * 0.5f) * bin_h;
        float xx = -w * 0.5f + ((float)pw + (sx + 0.5f) * 0.5f) * bin_w;
        float xs = cx + xx * cosT - yy * sinT;
        float ys = cy + xx * sinT + yy * cosT;
        bool valid = (ys > -1.0f) && (ys < (float)H) &&
                     (xs > -1.0f) && (xs < (float)W);
        float y = fminf(fmaxf(ys, 0.0f), (float)(H - 1));
        float x = fminf(fmaxf(xs, 0.0f), (float)(W - 1));
        int y0 = (int)floorf(y);
        int x0 = (int)floorf(x);
        int y1 = min(y0 + 1, H - 1);
        int x1 = min(x0 + 1, W - 1);
        float ly = y - (float)y0, lx = x - (float)x0;
        float hy = 1.0f - ly,     hx = 1.0f - lx;

        float sc = valid ? 0.25f : 0.0f;    // fold subsample mean + validity
        uint32_t r0 = (uint32_t)(y0 * W) * (uint32_t)C;
        uint32_t r1 = (uint32_t)(y1 * W) * (uint32_t)C;
        uint32_t c0 = (uint32_t)x0 * (uint32_t)C;
        uint32_t c1 = (uint32_t)x1 * (uint32_t)C;
        soff[s] = make_uint4(r0 + c0, r0 + c1, r1 + c0, r1 + c1);
        swt[s]  = make_float4(hy * hx * sc, hy * lx * sc, ly * hx * sc, ly * lx * sc);
    }
    __syncthreads();

    // ---- Phase B: thread = 2 channels; float2 gather + FMA ----
    int c = tid * 2;
    const float* fb = g_feat_t + (size_t)b * HW * C + c;   // even offset -> 8B aligned

    #pragma unroll 1
    for (int bin = 0; bin < PH * PW; bin++) {
        float ax = 0.0f, ay = 0.0f;
        #pragma unroll
        for (int sub = 0; sub < 4; sub++) {
            int s = bin * 4 + sub;
            uint4  o = soff[s];
            float4 wv = swt[s];
            float2 v00 = __ldg((const float2*)(fb + o.x));
            float2 v01 = __ldg((const float2*)(fb + o.y));
            float2 v10 = __ldg((const float2*)(fb + o.z));
            float2 v11 = __ldg((const float2*)(fb + o.w));
            ax += wv.x * v00.x + wv.y * v01.x + wv.z * v10.x + wv.w * v11.x;
            ay += wv.x * v00.y + wv.y * v01.y + wv.z * v10.y + wv.w * v11.y;
        }
        sacc[c * (PH * PW) + bin]       = ax;
        sacc[(c + 1) * (PH * PW) + bin] = ay;
    }
    __syncthreads();

    // ---- coalesced tf32-rounded writeout (float4 granularity) ----
    float* outrow = g_x + (size_t)m * D;
    for (int i = tid * 4; i < D; i += 128 * 4) {
        float4 v = *(const float4*)(sacc + i);
        v.x = tf32_round(v.x); v.y = tf32_round(v.y);
        v.z = tf32_round(v.z); v.w = tf32_round(v.w);
        *(float4*)(outrow + i) = v;
    }
}

// ---------------- 3. TF32 mma.sync GEMM: C[M,1024] = A[M,K] @ Bt[1024,K]^T ----------------
// 128x128 CTA tile, BK=32 floats, 8 warps (2x4), warp tile 64x32, 4-stage cp.async.
constexpr int SSTR   = 36;                 // smem row stride (floats), conflict-free
constexpr int STG_F  = 2 * 128 * SSTR;     // floats per stage (As + Bs)
constexpr int NSTG   = 4;
constexpr int SMEM_GEMM = NSTG * STG_F * 4;  // 147456 B

__global__ void __launch_bounds__(256) gemm_tf32_kernel(
    const float* __restrict__ A, const float* __restrict__ Bt,
    const float* __restrict__ bias, float* __restrict__ Cout,
    int Mi, int Ki, int flags)          // flags: bit0 relu, bit1 tf32-round output
{
    extern __shared__ float sm[];
    int tid  = threadIdx.x;
    int wid  = tid >> 5, lane = tid & 31;
    int gq   = lane >> 2;      // groupID 0..7
    int tq   = lane & 3;       // thread-in-group 0..3
    int wm   = wid >> 2;       // 0..1  (m)
    int wn   = wid & 3;        // 0..3  (n)
    int bm   = blockIdx.y * 128;
    int bn   = blockIdx.x * 128;

    // cp.async assignments: 2 threads per row, 4x16B each
    int ldRow  = tid >> 1;
    int ldColF = (tid & 1) * 16;
    int gmA    = bm + ldRow;
    bool aOk   = gmA < Mi;
    const float* gA = A  + (size_t)gmA * Ki + ldColF;
    const float* gB = Bt + (size_t)(bn + ldRow) * Ki + ldColF;
    uint32_t sA = smem_u32(sm) + (uint32_t)(ldRow * SSTR + ldColF) * 4u;
    uint32_t sB = sA + 128u * SSTR * 4u;

    const int NT = Ki / 32;

    // prologue: tiles 0,1,2
    #pragma unroll
    for (int s = 0; s < 3; s++) {
        uint32_t so = (uint32_t)(s * STG_F) * 4u;
        #pragma unroll
        for (int j = 0; j < 4; j++) {
            cpasync16(sA + so + j * 16u, gA + s * 32 + j * 4, aOk);
            cpasync16(sB + so + j * 16u, gB + s * 32 + j * 4, true);
        }
        cp_commit();
    }

    float acc[4][4][4];
    #pragma unroll
    for (int i = 0; i < 4; i++)
        #pragma unroll
        for (int j = 0; j < 4; j++)
            #pragma unroll
            for (int k = 0; k < 4; k++) acc[i][j][k] = 0.0f;

    int arb = wm * 64;          // warp row base within tile
    int bcb = wn * 32;          // warp col base within tile

    for (int kt = 0; kt < NT; kt++) {
        cp_wait2();
        __syncthreads();

        // issue loads for tile kt+3 into slot (kt+3)%4 (freed at iter kt-1)
        if (kt + 3 < NT) {
            uint32_t so = (uint32_t)(((kt + 3) & 3) * STG_F) * 4u;
            const float* pa = gA + (kt + 3) * 32;
            const float* pb = gB + (kt + 3) * 32;
            #pragma unroll
            for (int j = 0; j < 4; j++) {
                cpasync16(sA + so + j * 16u, pa + j * 4, aOk);
                cpasync16(sB + so + j * 16u, pb + j * 4, true);
            }
        }
        cp_commit();

        const float* smA = sm + (kt & 3) * STG_F;
        const float* smB = smA + 128 * SSTR;

        #pragma unroll
        for (int ks = 0; ks < 4; ks++) {
            int k0 = ks * 8;
            uint32_t af[4][4], bf[4][2];
            #pragma unroll
            for (int am = 0; am < 4; am++) {
                int r = arb + am * 16 + gq;
                af[am][0] = __float_as_uint(smA[r * SSTR + k0 + tq]);
                af[am][1] = __float_as_uint(smA[(r + 8) * SSTR + k0 + tq]);
                af[am][2] = __float_as_uint(smA[r * SSTR + k0 + tq + 4]);
                af[am][3] = __float_as_uint(smA[(r + 8) * SSTR + k0 + tq + 4]);
            }
            #pragma unroll
            for (int bq = 0; bq < 4; bq++) {
                int n = bcb + bq * 8 + gq;
                bf[bq][0] = __float_as_uint(smB[n * SSTR + k0 + tq]);
                bf[bq][1] = __float_as_uint(smB[n * SSTR + k0 + tq + 4]);
            }
            #pragma unroll
            for (int am = 0; am < 4; am++)
                #pragma unroll
                for (int bq = 0; bq < 4; bq++)
                    mma_tf32(acc[am][bq], af[am], bf[bq]);
        }
        // NOTE: no trailing __syncthreads needed — the barrier at the top of the
        // next iteration orders this iteration's MMA reads (slot kt&3) before the
        // next write to that slot (iter kt+1 writes slot (kt+4)&3 = kt&3, post-barrier).
    }

    // epilogue: bias + relu (+ tf32 round), write float2 pairs
    bool relu = flags & 1, rnd = flags & 2;
    #pragma unroll
    for (int am = 0; am < 4; am++) {
        int r0 = bm + arb + am * 16 + gq;
        #pragma unroll
        for (int bq = 0; bq < 4; bq++) {
            int cidx = bn + bcb + bq * 8 + tq * 2;
            float b0 = bias[cidx], b1 = bias[cidx + 1];
            #pragma unroll
            for (int half = 0; half < 2; half++) {
                int row = r0 + half * 8;
                if (row < Mi) {
                    float a0 = acc[am][bq][half * 2 + 0] + b0;
                    float a1 = acc[am][bq][half * 2 + 1] + b1;
                    if (relu) { a0 = fmaxf(a0, 0.f); a1 = fmaxf(a1, 0.f); }
                    if (rnd)  { a0 = tf32_round(a0); a1 = tf32_round(a1); }
                    float2 v = make_float2(a0, a1);
                    *(float2*)(Cout + (size_t)row * 1024 + cidx) = v;
                }
            }
        }
    }
}

// ---------------- 4. head: cls (11) + reg (5) ----------------
__global__ void __launch_bounds__(128) head_kernel(
    const float* __restrict__ wc, const float* __restrict__ bc,
    const float* __restrict__ wr, const float* __restrict__ br,
    float* __restrict__ out)
{
    int m = blockIdx.x;
    __shared__ float sx[OUT];
    const float* row = g_h2 + (size_t)m * OUT;
    for (int i = threadIdx.x; i < OUT; i += 128) sx[i] = row[i];
    __syncthreads();

    int o = threadIdx.x >> 3;   // 0..15
    int g = threadIdx.x & 7;
    float acc = 0.0f;
    if (o < NCLS) {
        for (int k = g; k < OUT; k += 8) acc += sx[k] * wc[(size_t)k * NCLS + o];
    } else {
        int oo = o - NCLS;
        for (int k = g; k < OUT; k += 8) acc += sx[k] * wr[(size_t)k * NREG + oo];
    }
    acc += __shfl_down_sync(0xffffffffu, acc, 4, 8);
    acc += __shfl_down_sync(0xffffffffu, acc, 2, 8);
    acc += __shfl_down_sync(0xffffffffu, acc, 1, 8);
    if (g == 0) {
        if (o < NCLS) out[(size_t)m * NCLS + o] = acc + bc[o];
        else out[(size_t)M * NCLS + (size_t)m * NREG + (o - NCLS)] = acc + br[o - NCLS];
    }
}

// ---------------- launch ----------------
extern "C" void kernel_launch(void* const* d_in, const int* in_sizes, int n_in,
                              void* d_out, int out_size)
{
    const float* feat = (const float*)d_in[0];
    const float* rois = (const float*)d_in[1];
    const float* w1   = (const float*)d_in[2];
    const float* b1   = (const float*)d_in[3];
    const float* w2   = (const float*)d_in[4];
    const float* b2   = (const float*)d_in[5];
    const float* wc   = (const float*)d_in[6];
    const float* bc   = (const float*)d_in[7];
    const float* wr   = (const float*)d_in[8];
    const float* br   = (const float*)d_in[9];
    float* out = (float*)d_out;

    float *xbuf, *w1t, *w2t, *h1, *h2;
    cudaGetSymbolAddress((void**)&xbuf, g_x);
    cudaGetSymbolAddress((void**)&w1t,  g_w1t);
    cudaGetSymbolAddress((void**)&w2t,  g_w2t);
    cudaGetSymbolAddress((void**)&h1,   g_h1);
    cudaGetSymbolAddress((void**)&h2,   g_h2);
    float* featT;
    cudaGetSymbolAddress((void**)&featT, g_feat_t);

    // 1. transposes: feat [B,C,HW]->[B,HW,C]; w1 [D,OUT]->[OUT,D]; w2 [OUT,OUT]->[OUT,OUT]
    {
        dim3 blk(32, 8);
        transpose_kernel<<<dim3(HW / 32, C / 32, B), blk>>>(feat, featT, C, HW, 0);
        transpose_kernel<<<dim3(OUT / 32, D / 32, 1), blk>>>(w1, w1t, D, OUT, 1);
        transpose_kernel<<<dim3(OUT / 32, OUT / 32, 1), blk>>>(w2, w2t, OUT, OUT, 1);
    }

    // 2. roi align
    {
        cudaFuncSetAttribute(roi_align_kernel,
                             cudaFuncAttributeMaxDynamicSharedMemorySize, ROI_SMEM);
        roi_align_kernel<<<M, 128, ROI_SMEM>>>(rois);
    }

    // 3. fc1 + fc2 on tf32 mma.sync tensor cores
    cudaFuncSetAttribute(gemm_tf32_kernel,
                         cudaFuncAttributeMaxDynamicSharedMemorySize, SMEM_GEMM);
    {
        dim3 grid(OUT / 128, (M + 127) / 128);   // (8, 16)
        gemm_tf32_kernel<<<grid, 256, SMEM_GEMM>>>(xbuf, w1t, b1, h1, M, D, 3);   // relu+round
        gemm_tf32_kernel<<<grid, 256, SMEM_GEMM>>>(h1, w2t, b2, h2, M, OUT, 1);   // relu
    }

    // 4. heads
    head_kernel<<<M, 128>>>(wc, bc, wr, br, out);
}

// round 9
// speedup vs baseline: 1.0552x; 1.0552x over previous
#include <cuda_runtime.h>
#include <cstddef>
#include <cstdint>

// ---------------- problem constants ----------------
constexpr int B      = 2;
constexpr int C      = 256;
constexpr int H      = 256;
constexpr int W      = 256;
constexpr int NROI   = 1000;
constexpr int PH     = 7;
constexpr int PW     = 7;
constexpr int OUT    = 1024;
constexpr int NCLS   = 11;    // NUM_CLASSES + 1
constexpr int NREG   = 5;
constexpr int D      = C * PH * PW;   // 12544
constexpr int M      = B * NROI;      // 2000
constexpr int HW     = H * W;
constexpr int NSAMP  = PH * PW * 4;   // 196

// ---------------- scratch (static device globals; no allocation) ----------------
__device__ float g_feat_t[(size_t)B * HW * C];   // [B, H, W, C]
__device__ float g_x[(size_t)M * D];             // aligned features (tf32-rounded)
__device__ float g_w1t[(size_t)OUT * D];         // w1 transposed [N,K] (tf32-rounded)
__device__ float g_w2t[(size_t)OUT * OUT];       // w2 transposed
__device__ float g_h1[(size_t)M * OUT];
__device__ float g_h2[(size_t)M * OUT];

// ---------------- helpers ----------------
__device__ __forceinline__ uint32_t smem_u32(const void* p) {
    uint32_t a;
    asm("{ .reg .u64 t; cvta.to.shared.u64 t, %1; cvt.u32.u64 %0, t; }" : "=r"(a) : "l"(p));
    return a;
}
__device__ __forceinline__ float tf32_round(float x) {
    uint32_t u;
    asm("cvt.rna.tf32.f32 %0, %1;" : "=r"(u) : "f"(x));
    return __uint_as_float(u);
}
__device__ __forceinline__ void cpasync16(uint32_t s, const void* g, bool pred) {
    int sz = pred ? 16 : 0;
    asm volatile("cp.async.cg.shared.global [%0], [%1], 16, %2;"
                 :: "r"(s), "l"(g), "r"(sz) : "memory");
}
__device__ __forceinline__ void cp_commit() {
    asm volatile("cp.async.commit_group;" ::: "memory");
}
__device__ __forceinline__ void cp_wait2() {
    asm volatile("cp.async.wait_group 2;" ::: "memory");
}
__device__ __forceinline__ void mma_tf32(float* d, const uint32_t* a, const uint32_t* b) {
    asm volatile(
        "mma.sync.aligned.m16n8k8.row.col.f32.tf32.tf32.f32 "
        "{%0,%1,%2,%3}, {%4,%5,%6,%7}, {%8,%9}, {%0,%1,%2,%3};"
        : "+f"(d[0]), "+f"(d[1]), "+f"(d[2]), "+f"(d[3])
        : "r"(a[0]), "r"(a[1]), "r"(a[2]), "r"(a[3]), "r"(b[0]), "r"(b[1]));
}

// ---------------- 1. generic 32x32 transpose: in[z][R][Cc] -> out[z][Cc][R] ----------------
__global__ void transpose_kernel(const float* __restrict__ in, float* __restrict__ out,
                                 int R, int Cc, int doRound) {
    __shared__ float tile[32][33];
    size_t zo = (size_t)blockIdx.z * R * Cc;
    int c0 = blockIdx.x * 32;
    int r0 = blockIdx.y * 32;
    int tx = threadIdx.x, ty = threadIdx.y;
    #pragma unroll
    for (int i = 0; i < 32; i += 8)
        tile[ty + i][tx] = in[zo + (size_t)(r0 + ty + i) * Cc + c0 + tx];
    __syncthreads();
    #pragma unroll
    for (int i = 0; i < 32; i += 8) {
        float v = tile[tx][ty + i];
        if (doRound) v = tf32_round(v);
        out[zo + (size_t)(c0 + ty + i) * R + r0 + tx] = v;
    }
}

// ---------------- 2. rotated RoI align: geometry + float2 gather, bin-split ----------------
// one roi per 256-thread block; thread = (tid&127) channel-pair; tid>>7 picks bin half
constexpr int ROI_SMEM = D * 4 + NSAMP * 32;   // 56448 B

__global__ void __launch_bounds__(256) roi_align_kernel(const float* __restrict__ rois) {
    extern __shared__ float sacc[];                       // [D]
    uint4*  soff = (uint4*)(sacc + D);                    // [NSAMP]
    float4* swt  = (float4*)(soff + NSAMP);               // [NSAMP]

    int m = blockIdx.x;
    int b = m / NROI;
    int tid = threadIdx.x;

    // ---- Phase A: geometry, 196 samples on first 196 threads ----
    if (tid < NSAMP) {
        const float* rp = rois + (size_t)m * 5;
        float cx = rp[0], cy = rp[1], w = rp[2], h = rp[3], th = rp[4];
        float cosT = cosf(th), sinT = sinf(th);
        float bin_h = h * (1.0f / PH);
        float bin_w = w * (1.0f / PW);

        int bin = tid >> 2;          // 0..48
        int sub = tid & 3;           // 0..3
        int ph  = bin / PW;
        int pw  = bin % PW;
        int sy  = sub >> 1;
        int sx  = sub & 1;

        float yy = -h * 0.5f + ((float)ph + (sy + 0.5f) * 0.5f) * bin_h;
        float xx = -w * 0.5f + ((float)pw + (sx + 0.5f) * 0.5f) * bin_w;
        float xs = cx + xx * cosT - yy * sinT;
        float ys = cy + xx * sinT + yy * cosT;
        bool valid = (ys > -1.0f) && (ys < (float)H) &&
                     (xs > -1.0f) && (xs < (float)W);
        float y = fminf(fmaxf(ys, 0.0f), (float)(H - 1));
        float x = fminf(fmaxf(xs, 0.0f), (float)(W - 1));
        int y0 = (int)floorf(y);
        int x0 = (int)floorf(x);
        int y1 = min(y0 + 1, H - 1);
        int x1 = min(x0 + 1, W - 1);
        float ly = y - (float)y0, lx = x - (float)x0;
        float hy = 1.0f - ly,     hx = 1.0f - lx;

        float sc = valid ? 0.25f : 0.0f;    // fold subsample mean + validity
        uint32_t r0 = (uint32_t)(y0 * W) * (uint32_t)C;
        uint32_t r1 = (uint32_t)(y1 * W) * (uint32_t)C;
        uint32_t c0 = (uint32_t)x0 * (uint32_t)C;
        uint32_t c1 = (uint32_t)x1 * (uint32_t)C;
        soff[tid] = make_uint4(r0 + c0, r0 + c1, r1 + c0, r1 + c1);
        swt[tid]  = make_float4(hy * hx * sc, hy * lx * sc, ly * hx * sc, ly * lx * sc);
    }
    __syncthreads();

    // ---- Phase B: 2 channels/thread, bins split across half-blocks ----
    int half = tid >> 7;                 // 0 or 1
    int c = (tid & 127) * 2;
    int bin0 = half ? 25 : 0;
    int bin1 = half ? 49 : 25;
    const float* fb = g_feat_t + (size_t)b * HW * C + c;   // even offset -> 8B aligned

    #pragma unroll 1
    for (int bin = bin0; bin < bin1; bin++) {
        float ax = 0.0f, ay = 0.0f;
        #pragma unroll
        for (int sub = 0; sub < 4; sub++) {
            int s = bin * 4 + sub;
            uint4  o = soff[s];
            float4 wv = swt[s];
            float2 v00 = __ldg((const float2*)(fb + o.x));
            float2 v01 = __ldg((const float2*)(fb + o.y));
            float2 v10 = __ldg((const float2*)(fb + o.z));
            float2 v11 = __ldg((const float2*)(fb + o.w));
            ax += wv.x * v00.x + wv.y * v01.x + wv.z * v10.x + wv.w * v11.x;
            ay += wv.x * v00.y + wv.y * v01.y + wv.z * v10.y + wv.w * v11.y;
        }
        sacc[c * (PH * PW) + bin]       = ax;
        sacc[(c + 1) * (PH * PW) + bin] = ay;
    }
    __syncthreads();

    // ---- coalesced tf32-rounded writeout (float4 granularity) ----
    float* outrow = g_x + (size_t)m * D;
    for (int i = tid * 4; i < D; i += 256 * 4) {
        float4 v = *(const float4*)(sacc + i);
        v.x = tf32_round(v.x); v.y = tf32_round(v.y);
        v.z = tf32_round(v.z); v.w = tf32_round(v.w);
        *(float4*)(outrow + i) = v;
    }
}

// ---------------- 3. TF32 mma.sync GEMM: C[M,1024] = A[M,K] @ Bt[1024,K]^T ----------------
// 128x128 CTA tile, BK=32, 8 warps (2x4), warp tile 64x32, 4-stage cp.async,
// fragment double-buffering across ks sub-steps.
constexpr int SSTR   = 36;                 // smem row stride (floats), conflict-free
constexpr int STG_F  = 2 * 128 * SSTR;     // floats per stage (As + Bs)
constexpr int NSTG   = 4;
constexpr int SMEM_GEMM = NSTG * STG_F * 4;  // 147456 B

__global__ void __launch_bounds__(256) gemm_tf32_kernel(
    const float* __restrict__ A, const float* __restrict__ Bt,
    const float* __restrict__ bias, float* __restrict__ Cout,
    int Mi, int Ki, int flags)          // flags: bit0 relu, bit1 tf32-round output
{
    extern __shared__ float sm[];
    int tid  = threadIdx.x;
    int wid  = tid >> 5, lane = tid & 31;
    int gq   = lane >> 2;      // groupID 0..7
    int tq   = lane & 3;       // thread-in-group 0..3
    int wm   = wid >> 2;       // 0..1  (m)
    int wn   = wid & 3;        // 0..3  (n)
    int bm   = blockIdx.y * 128;
    int bn   = blockIdx.x * 128;

    // cp.async assignments: 2 threads per row, 4x16B each
    int ldRow  = tid >> 1;
    int ldColF = (tid & 1) * 16;
    int gmA    = bm + ldRow;
    bool aOk   = gmA < Mi;
    const float* gA = A  + (size_t)gmA * Ki + ldColF;
    const float* gB = Bt + (size_t)(bn + ldRow) * Ki + ldColF;
    uint32_t sA = smem_u32(sm) + (uint32_t)(ldRow * SSTR + ldColF) * 4u;
    uint32_t sB = sA + 128u * SSTR * 4u;

    const int NT = Ki / 32;

    // prologue: tiles 0,1,2
    #pragma unroll
    for (int s = 0; s < 3; s++) {
        uint32_t so = (uint32_t)(s * STG_F) * 4u;
        #pragma unroll
        for (int j = 0; j < 4; j++) {
            cpasync16(sA + so + j * 16u, gA + s * 32 + j * 4, aOk);
            cpasync16(sB + so + j * 16u, gB + s * 32 + j * 4, true);
        }
        cp_commit();
    }

    float acc[4][4][4];
    #pragma unroll
    for (int i = 0; i < 4; i++)
        #pragma unroll
        for (int j = 0; j < 4; j++)
            #pragma unroll
            for (int k = 0; k < 4; k++) acc[i][j][k] = 0.0f;

    int arb = wm * 64;          // warp row base within tile
    int bcb = wn * 32;          // warp col base within tile

    for (int kt = 0; kt < NT; kt++) {
        cp_wait2();
        __syncthreads();

        // issue loads for tile kt+3 into slot (kt+3)%4 (freed at iter kt-1)
        if (kt + 3 < NT) {
            uint32_t so = (uint32_t)(((kt + 3) & 3) * STG_F) * 4u;
            const float* pa = gA + (kt + 3) * 32;
            const float* pb = gB + (kt + 3) * 32;
            #pragma unroll
            for (int j = 0; j < 4; j++) {
                cpasync16(sA + so + j * 16u, pa + j * 4, aOk);
                cpasync16(sB + so + j * 16u, pb + j * 4, true);
            }
        }
        cp_commit();

        const float* smA = sm + (kt & 3) * STG_F;
        const float* smB = smA + 128 * SSTR;

        // fragment double-buffer across ks sub-steps
        uint32_t af[2][4][4], bf[2][4][2];

        // load ks=0 fragments
        #pragma unroll
        for (int am = 0; am < 4; am++) {
            int r = arb + am * 16 + gq;
            af[0][am][0] = __float_as_uint(smA[r * SSTR + tq]);
            af[0][am][1] = __float_as_uint(smA[(r + 8) * SSTR + tq]);
            af[0][am][2] = __float_as_uint(smA[r * SSTR + tq + 4]);
            af[0][am][3] = __float_as_uint(smA[(r + 8) * SSTR + tq + 4]);
        }
        #pragma unroll
        for (int bq = 0; bq < 4; bq++) {
            int n = bcb + bq * 8 + gq;
            bf[0][bq][0] = __float_as_uint(smB[n * SSTR + tq]);
            bf[0][bq][1] = __float_as_uint(smB[n * SSTR + tq + 4]);
        }

        #pragma unroll
        for (int ks = 0; ks < 4; ks++) {
            int cur = ks & 1, nxt = cur ^ 1;
            if (ks < 3) {
                int k0 = (ks + 1) * 8;
                #pragma unroll
                for (int am = 0; am < 4; am++) {
                    int r = arb + am * 16 + gq;
                    af[nxt][am][0] = __float_as_uint(smA[r * SSTR + k0 + tq]);
                    af[nxt][am][1] = __float_as_uint(smA[(r + 8) * SSTR + k0 + tq]);
                    af[nxt][am][2] = __float_as_uint(smA[r * SSTR + k0 + tq + 4]);
                    af[nxt][am][3] = __float_as_uint(smA[(r + 8) * SSTR + k0 + tq + 4]);
                }
                #pragma unroll
                for (int bq = 0; bq < 4; bq++) {
                    int n = bcb + bq * 8 + gq;
                    bf[nxt][bq][0] = __float_as_uint(smB[n * SSTR + k0 + tq]);
                    bf[nxt][bq][1] = __float_as_uint(smB[n * SSTR + k0 + tq + 4]);
                }
            }
            #pragma unroll
            for (int am = 0; am < 4; am++)
                #pragma unroll
                for (int bq = 0; bq < 4; bq++)
                    mma_tf32(acc[am][bq], af[cur][am], bf[cur][bq]);
        }
        // no trailing __syncthreads: next iteration's top barrier provides ordering
    }

    // epilogue: bias + relu (+ tf32 round), write float2 pairs
    bool relu = flags & 1, rnd = flags & 2;
    #pragma unroll
    for (int am = 0; am < 4; am++) {
        int r0 = bm + arb + am * 16 + gq;
        #pragma unroll
        for (int bq = 0; bq < 4; bq++) {
            int cidx = bn + bcb + bq * 8 + tq * 2;
            float b0 = bias[cidx], b1 = bias[cidx + 1];
            #pragma unroll
            for (int half = 0; half < 2; half++) {
                int row = r0 + half * 8;
                if (row < Mi) {
                    float a0 = acc[am][bq][half * 2 + 0] + b0;
                    float a1 = acc[am][bq][half * 2 + 1] + b1;
                    if (relu) { a0 = fmaxf(a0, 0.f); a1 = fmaxf(a1, 0.f); }
                    if (rnd)  { a0 = tf32_round(a0); a1 = tf32_round(a1); }
                    float2 v = make_float2(a0, a1);
                    *(float2*)(Cout + (size_t)row * 1024 + cidx) = v;
                }
            }
        }
    }
}

// ---------------- 4. head: cls (11) + reg (5) ----------------
__global__ void __launch_bounds__(128) head_kernel(
    const float* __restrict__ wc, const float* __restrict__ bc,
    const float* __restrict__ wr, const float* __restrict__ br,
    float* __restrict__ out)
{
    int m = blockIdx.x;
    __shared__ float sx[OUT];
    const float* row = g_h2 + (size_t)m * OUT;
    for (int i = threadIdx.x; i < OUT; i += 128) sx[i] = row[i];
    __syncthreads();

    int o = threadIdx.x >> 3;   // 0..15
    int g = threadIdx.x & 7;
    float acc = 0.0f;
    if (o < NCLS) {
        for (int k = g; k < OUT; k += 8) acc += sx[k] * wc[(size_t)k * NCLS + o];
    } else {
        int oo = o - NCLS;
        for (int k = g; k < OUT; k += 8) acc += sx[k] * wr[(size_t)k * NREG + oo];
    }
    acc += __shfl_down_sync(0xffffffffu, acc, 4, 8);
    acc += __shfl_down_sync(0xffffffffu, acc, 2, 8);
    acc += __shfl_down_sync(0xffffffffu, acc, 1, 8);
    if (g == 0) {
        if (o < NCLS) out[(size_t)m * NCLS + o] = acc + bc[o];
        else out[(size_t)M * NCLS + (size_t)m * NREG + (o - NCLS)] = acc + br[o - NCLS];
    }
}

// ---------------- launch ----------------
extern "C" void kernel_launch(void* const* d_in, const int* in_sizes, int n_in,
                              void* d_out, int out_size)
{
    const float* feat = (const float*)d_in[0];
    const float* rois = (const float*)d_in[1];
    const float* w1   = (const float*)d_in[2];
    const float* b1   = (const float*)d_in[3];
    const float* w2   = (const float*)d_in[4];
    const float* b2   = (const float*)d_in[5];
    const float* wc   = (const float*)d_in[6];
    const float* bc   = (const float*)d_in[7];
    const float* wr   = (const float*)d_in[8];
    const float* br   = (const float*)d_in[9];
    float* out = (float*)d_out;

    float *xbuf, *w1t, *w2t, *h1, *h2;
    cudaGetSymbolAddress((void**)&xbuf, g_x);
    cudaGetSymbolAddress((void**)&w1t,  g_w1t);
    cudaGetSymbolAddress((void**)&w2t,  g_w2t);
    cudaGetSymbolAddress((void**)&h1,   g_h1);
    cudaGetSymbolAddress((void**)&h2,   g_h2);
    float* featT;
    cudaGetSymbolAddress((void**)&featT, g_feat_t);

    // 1. transposes: feat [B,C,HW]->[B,HW,C]; w1 [D,OUT]->[OUT,D]; w2 [OUT,OUT]->[OUT,OUT]
    {
        dim3 blk(32, 8);
        transpose_kernel<<<dim3(HW / 32, C / 32, B), blk>>>(feat, featT, C, HW, 0);
        transpose_kernel<<<dim3(OUT / 32, D / 32, 1), blk>>>(w1, w1t, D, OUT, 1);
        transpose_kernel<<<dim3(OUT / 32, OUT / 32, 1), blk>>>(w2, w2t, OUT, OUT, 1);
    }

    // 2. roi align
    {
        cudaFuncSetAttribute(roi_align_kernel,
                             cudaFuncAttributeMaxDynamicSharedMemorySize, ROI_SMEM);
        roi_align_kernel<<<M, 256, ROI_SMEM>>>(rois);
    }

    // 3. fc1 + fc2 on tf32 mma.sync tensor cores
    cudaFuncSetAttribute(gemm_tf32_kernel,
                         cudaFuncAttributeMaxDynamicSharedMemorySize, SMEM_GEMM);
    {
        dim3 grid(OUT / 128, (M + 127) / 128);   // (8, 16)
        gemm_tf32_kernel<<<grid, 256, SMEM_GEMM>>>(xbuf, w1t, b1, h1, M, D, 3);   // relu+round
        gemm_tf32_kernel<<<grid, 256, SMEM_GEMM>>>(h1, w2t, b2, h2, M, OUT, 1);   // relu
    }

    // 4. heads
    head_kernel<<<M, 128>>>(wc, bc, wr, br, out);
}